// round 1
// baseline (speedup 1.0000x reference)
#include <cuda_runtime.h>

// Problem constants (match reference_code)
#define NB   64      // batch
#define NT   2048    // seq len
#define EMBD 32
#define HID  256
#define KTOT (EMBD + HID)   // 288
#define NCTA 128            // 2 hidden units per CTA
#define UPC  2
#define NROWS (4 * UPC)     // 8 gate rows per CTA
#define NTHREADS 128

// Persistent cross-CTA state (no cudaMalloc allowed)
__device__ float g_H[2][HID * NB];          // [buf][unit*NB + b], double buffered
__device__ unsigned g_count;
__device__ volatile unsigned g_release;

__global__ void lstm_init_kernel() {
    g_count = 0u;
    g_release = 0u;
}

__device__ __forceinline__ float sigf(float x)  { return 1.0f / (1.0f + __expf(-x)); }
__device__ __forceinline__ float tanha(float x) { return 2.0f / (1.0f + __expf(-2.0f * x)) - 1.0f; }

__global__ void __launch_bounds__(NTHREADS, 1)
lstm_persist_kernel(const int* __restrict__ x,        // [NB, NT] int32
                    const int* __restrict__ lengths,  // [NB] int32
                    const float* __restrict__ emb,    // [VOCAB, EMBD]
                    const float* __restrict__ W_ih,   // [4*HID, EMBD]
                    const float* __restrict__ W_hh,   // [4*HID, HID]
                    const float* __restrict__ b_ih,   // [4*HID]
                    const float* __restrict__ b_hh,   // [4*HID]
                    float* __restrict__ out)          // [NB, 1, HID]
{
    extern __shared__ float sm[];
    float* z_s    = sm;                        // [KTOT][NB]   (xe rows 0..31, h rows 32..287)
    float* w_s    = z_s + KTOT * NB;           // [KTOT][NROWS]
    float* gate_s = w_s + KTOT * NROWS;        // [NROWS][NB]
    float* bias_s = gate_s + NROWS * NB;       // [NROWS]
    int*   len_s  = (int*)(bias_s + NROWS);    // [NB]
    int*   ml_s   = len_s + NB;                // [1]

    const int tid = threadIdx.x;
    const int cta = blockIdx.x;
    const int u0  = cta * UPC;                 // first hidden unit owned by this CTA

    // ---- one-time staging: weights (transposed to [k][row]), bias, lengths ----
    for (int idx = tid; idx < NROWS * KTOT; idx += NTHREADS) {
        int lr = idx / KTOT;
        int k  = idx - lr * KTOT;
        int gate = lr >> 1, du = lr & 1;
        int grow = gate * HID + u0 + du;       // global row in W (i,f,g,o blocks of 256)
        float v = (k < EMBD) ? W_ih[grow * EMBD + k]
                             : W_hh[grow * HID + (k - EMBD)];
        w_s[k * NROWS + lr] = v;
    }
    if (tid < NROWS) {
        int gate = tid >> 1, du = tid & 1;
        int grow = gate * HID + u0 + du;
        bias_s[tid] = b_ih[grow] + b_hh[grow];
    }
    if (tid < NB) len_s[tid] = lengths[tid];
    // zero the h rows of z for step 0
    for (int i = tid; i < HID * NB; i += NTHREADS) z_s[EMBD * NB + i] = 0.0f;
    __syncthreads();
    if (tid == 0) {
        int m = 1;
        for (int b = 0; b < NB; b++) m = max(m, len_s[b]);
        *ml_s = m;
    }
    __syncthreads();
    const int maxlen = *ml_s;

    // compute-phase mapping: warp w covers rows 0..7 x batches [16w,16w+16)
    // thread tile: 2 gate-rows x 2 batches (float2 LDS both sides)
    const int lane = tid & 31, wrp = tid >> 5;
    const int lr0 = (lane >> 3) << 1;                 // 0,2,4,6
    const int b0  = (wrp << 4) + ((lane & 7) << 1);   // even batch index

    // phase-2 mapping: one (unit,batch) per thread; c/h live in registers
    const int du2 = tid >> 6;          // 0..1 (unit within CTA)
    const int b2  = tid & 63;          // batch
    const int hrow = (u0 + du2) * NB + b2;
    const int mylen = len_s[b2];
    float c_r = 0.0f, h_r = 0.0f;

    for (int t = 0; t < maxlen; t++) {
        // ---- stage h from global double buffer (skip at t=0: zeros already) ----
        if (t > 0) {
            const float4* src = (const float4*)g_H[t & 1];
            float4* dst = (float4*)(z_s + EMBD * NB);
            #pragma unroll
            for (int i = 0; i < (HID * NB / 4) / NTHREADS; i++)
                dst[tid + i * NTHREADS] = src[tid + i * NTHREADS];
        }
        // ---- stage xe: gather embedding rows for all 64 batches ----
        if (tid < NB) {
            int tok = x[tid * NT + t];
            tok = min(max(tok, 0), 31999);   // defensive clamp
            const float4* e = (const float4*)(emb + (long)tok * EMBD);
            #pragma unroll
            for (int q = 0; q < EMBD / 4; q++) {
                float4 v = e[q];
                z_s[(q * 4 + 0) * NB + tid] = v.x;
                z_s[(q * 4 + 1) * NB + tid] = v.y;
                z_s[(q * 4 + 2) * NB + tid] = v.z;
                z_s[(q * 4 + 3) * NB + tid] = v.w;
            }
        }
        __syncthreads();

        // ---- gates = W . z  (2 rows x 2 batches per thread) ----
        float bw0 = bias_s[lr0], bw1 = bias_s[lr0 + 1];
        float a00 = bw0, a01 = bw0, a10 = bw1, a11 = bw1;
        #pragma unroll 8
        for (int k = 0; k < KTOT; k++) {
            float2 wv = *(const float2*)(w_s + k * NROWS + lr0);
            float2 zv = *(const float2*)(z_s + k * NB + b0);
            a00 = fmaf(wv.x, zv.x, a00);
            a01 = fmaf(wv.x, zv.y, a01);
            a10 = fmaf(wv.y, zv.x, a10);
            a11 = fmaf(wv.y, zv.y, a11);
        }
        *(float2*)(gate_s + lr0 * NB + b0)       = make_float2(a00, a01);
        *(float2*)(gate_s + (lr0 + 1) * NB + b0) = make_float2(a10, a11);
        __syncthreads();

        // ---- phase 2: activations + state update (one (unit,batch) per thread) ----
        {
            float gi = gate_s[(0 + du2) * NB + b2];
            float gf = gate_s[(2 + du2) * NB + b2];
            float gg = gate_s[(4 + du2) * NB + b2];
            float go = gate_s[(6 + du2) * NB + b2];
            float iv = sigf(gi), fv = sigf(gf), gv = tanha(gg), ov = sigf(go);
            float cn = fmaf(fv, c_r, iv * gv);
            float hn = ov * tanha(cn);
            if (t < mylen) { c_r = cn; h_r = hn; }   // mask: freeze past length
            g_H[(t & 1) ^ 1][hrow] = h_r;            // write next step's read buffer
        }

        // ---- grid barrier (skip after last step) ----
        if (t + 1 < maxlen) {
            __syncthreads();                 // all CTA h-writes issued
            if (tid == 0) {
                __threadfence();             // release (cumulative over CTA barrier)
                unsigned old = atomicAdd(&g_count, 1u);
                if (old == NCTA - 1) {
                    atomicExch(&g_count, 0u);
                    __threadfence();
                    g_release = (unsigned)(t + 1);
                } else {
                    while (g_release < (unsigned)(t + 1)) { }
                }
                __threadfence();             // acquire
            }
            __syncthreads();
        }
    }

    // final h (frozen at t = length-1) == reference out[:, -1, :]
    out[b2 * HID + (u0 + du2)] = h_r;
}

extern "C" void kernel_launch(void* const* d_in, const int* in_sizes, int n_in,
                              void* d_out, int out_size) {
    const int*   x       = (const int*)d_in[0];
    const int*   lengths = (const int*)d_in[1];
    const float* emb     = (const float*)d_in[2];
    const float* W_ih    = (const float*)d_in[3];
    const float* W_hh    = (const float*)d_in[4];
    const float* b_ih    = (const float*)d_in[5];
    const float* b_hh    = (const float*)d_in[6];
    float* out = (float*)d_out;

    const int smem_bytes =
        (KTOT * NB + KTOT * NROWS + NROWS * NB + NROWS) * (int)sizeof(float)
        + (NB + 1) * (int)sizeof(int) + 16;

    cudaFuncSetAttribute(lstm_persist_kernel,
                         cudaFuncAttributeMaxDynamicSharedMemorySize, smem_bytes);

    lstm_init_kernel<<<1, 1>>>();
    lstm_persist_kernel<<<NCTA, NTHREADS, smem_bytes>>>(
        x, lengths, emb, W_ih, W_hh, b_ih, b_hh, out);
}

// round 2
// speedup vs baseline: 1.1817x; 1.1817x over previous
#include <cuda_runtime.h>
#include <cstdint>

// Problem constants
#define NB   64
#define NT   2048
#define EMBD 32
#define HID  256
#define KTOT (EMBD + HID)    // 288
#define USLICE 32            // unit slices
#define BSLICE 4             // batch slices
#define NCTA  (USLICE * BSLICE)   // 128
#define UPC   8              // units per CTA
#define NROWS (4 * UPC)      // 32 gate rows per CTA
#define BPC   16             // batches per CTA
#define NTHREADS 128

// Persistent cross-CTA state (no cudaMalloc allowed)
__device__ float g_H[2][HID * NB];   // [buf][unit*NB + batch]
__device__ unsigned g_count;
__device__ volatile unsigned g_release;

__global__ void lstm_init_kernel() { g_count = 0u; g_release = 0u; }

__device__ __forceinline__ float sigf(float x)  { return 1.0f / (1.0f + __expf(-x)); }
__device__ __forceinline__ float tanha(float x) { return 2.0f / (1.0f + __expf(-2.0f * x)) - 1.0f; }

// packed f32x2 helpers
#define PACK2(out, v) \
    asm("mov.b64 %0, {%1, %1};" : "=l"(out) : "r"(__float_as_uint(v)))

__global__ void __launch_bounds__(NTHREADS, 1)
lstm_persist_kernel(const int* __restrict__ x,        // [NB, NT]
                    const int* __restrict__ lengths,  // [NB]
                    const float* __restrict__ emb,    // [VOCAB, EMBD]
                    const float* __restrict__ W_ih,   // [4*HID, EMBD]
                    const float* __restrict__ W_hh,   // [4*HID, HID]
                    const float* __restrict__ b_ih,   // [4*HID]
                    const float* __restrict__ b_hh,   // [4*HID]
                    float* __restrict__ out)          // [NB, 1, HID]
{
    extern __shared__ float sm[];
    // layout (floats):
    float* w2   = sm;                          // [KTOT][NROWS][2]  splat pairs (73728 B)
    float* z    = w2 + KTOT * NROWS * 2;       // [KTOT][BPC]       (18432 B)
    float* gs   = z + KTOT * BPC;              // [NROWS][BPC]      (2048 B)
    float* bs   = gs + NROWS * BPC;            // [NROWS]
    int* lenS   = (int*)(bs + NROWS);          // [NB]
    int* mlS    = lenS + NB;

    const int tid = threadIdx.x;
    const int cta = blockIdx.x;
    const int us  = cta >> 2;        // unit slice 0..31
    const int bsl = cta & 3;         // batch slice 0..3
    const int u0  = us * UPC;
    const int bb0 = bsl * BPC;

    // ---- one-time staging ----
    for (int idx = tid; idx < NROWS * KTOT; idx += NTHREADS) {
        int r = idx / KTOT;
        int k = idx - r * KTOT;
        int g = r >> 3, du = r & 7;
        int grow = g * HID + u0 + du;
        float v = (k < EMBD) ? W_ih[grow * EMBD + k]
                             : W_hh[grow * HID + (k - EMBD)];
        w2[(k * NROWS + r) * 2 + 0] = v;
        w2[(k * NROWS + r) * 2 + 1] = v;
    }
    if (tid < NROWS) {
        int g = tid >> 3, du = tid & 7;
        int grow = g * HID + u0 + du;
        bs[tid] = b_ih[grow] + b_hh[grow];
    }
    if (tid < NB) lenS[tid] = lengths[tid];
    __syncthreads();
    if (tid == 0) {
        int m = 1;
        for (int b = 0; b < NB; b++) m = max(m, lenS[b]);
        *mlS = m;
    }
    // zero h region of z (for t=0)
    for (int i = tid; i < HID * BPC; i += NTHREADS) z[EMBD * BPC + i] = 0.0f;
    // gather xe(0)
    if (tid < BPC) {
        int tok = x[(bb0 + tid) * NT + 0];
        const float4* e = (const float4*)(emb + (long)tok * EMBD);
        #pragma unroll
        for (int q = 0; q < EMBD / 4; q++) {
            float4 v = e[q];
            z[(q * 4 + 0) * BPC + tid] = v.x;
            z[(q * 4 + 1) * BPC + tid] = v.y;
            z[(q * 4 + 2) * BPC + tid] = v.z;
            z[(q * 4 + 3) * BPC + tid] = v.w;
        }
    }
    __syncthreads();
    const int maxlen = *mlS;

    // smem base as 32-bit shared address for asm
    uint32_t sb;
    asm("{ .reg .u64 t; cvta.to.shared.u64 t, %1; cvt.u32.u64 %0, t; }"
        : "=r"(sb) : "l"(sm));
    const uint32_t ZOFF = (uint32_t)(KTOT * NROWS * 2) * 4u;
    const uint32_t GOFF = ZOFF + (uint32_t)(KTOT * BPC) * 4u;

    // GEMM thread mapping: rp = row-pair (0..15), batches b0,b0+1
    const int lane = tid & 31, wrp = tid >> 5;
    const int rp = lane >> 1, bp = lane & 1;
    const int r0 = rp * 2;
    const int b0 = wrp * 4 + bp * 2;
    const uint32_t wbase = sb + (uint32_t)(rp * 16);          // + k*256
    const uint32_t zbase = sb + ZOFF + (uint32_t)(b0 * 4);    // + k*64
    const uint32_t gadr0 = sb + GOFF + (uint32_t)((r0 * BPC + b0) * 4);
    const uint32_t gadr1 = sb + GOFF + (uint32_t)(((r0 + 1) * BPC + b0) * 4);
    const float bias0 = bs[r0], bias1 = bs[r0 + 1];

    // phase-2 mapping: one (unit,batch) per thread
    const int du2 = tid >> 4, b2l = tid & 15;
    const int bg = bb0 + b2l;
    const int uu = u0 + du2;
    const int mylen = lenS[bg];
    const int hidx = uu * NB + bg;
    float c_r = 0.0f, h_r = 0.0f;

    unsigned long long A0, A1;

    // ---- prologue: acc = bias + W_ih . xe(0) ----
    PACK2(A0, bias0);
    PACK2(A1, bias1);
    #pragma unroll 8
    for (int k = 0; k < EMBD; k++) {
        unsigned long long W0, W1, Z;
        asm volatile("ld.shared.v2.u64 {%0,%1}, [%2];"
                     : "=l"(W0), "=l"(W1) : "r"(wbase + (uint32_t)(k * 256)));
        asm volatile("ld.shared.u64 %0, [%1];"
                     : "=l"(Z) : "r"(zbase + (uint32_t)(k * 64)));
        asm volatile("fma.rn.f32x2 %0, %1, %2, %0;" : "+l"(A0) : "l"(W0), "l"(Z));
        asm volatile("fma.rn.f32x2 %0, %1, %2, %0;" : "+l"(A1) : "l"(W1), "l"(Z));
    }

    for (int t = 0; t < maxlen; t++) {
        // ---- stage h(t-1) from global double buffer ----
        if (t > 0) {
            const float* hb = g_H[t & 1];
            #pragma unroll
            for (int i = 0; i < 8; i++) {
                int idx = i * NTHREADS + tid;
                int un = idx >> 2;
                int bo = (idx & 3) * 4;
                float4 v = *(const float4*)(hb + un * NB + bb0 + bo);
                *(float4*)(z + (EMBD + un) * BPC + bo) = v;
            }
        }
        __syncthreads();

        // ---- acc += W_hh . h  (k = 32..287) ----
        {
            const uint32_t wk = wbase + (uint32_t)(EMBD * 256);
            const uint32_t zk = zbase + (uint32_t)(EMBD * 64);
            #pragma unroll 8
            for (int k = 0; k < HID; k++) {
                unsigned long long W0, W1, Z;
                asm volatile("ld.shared.v2.u64 {%0,%1}, [%2];"
                             : "=l"(W0), "=l"(W1) : "r"(wk + (uint32_t)(k * 256)));
                asm volatile("ld.shared.u64 %0, [%1];"
                             : "=l"(Z) : "r"(zk + (uint32_t)(k * 64)));
                asm volatile("fma.rn.f32x2 %0, %1, %2, %0;" : "+l"(A0) : "l"(W0), "l"(Z));
                asm volatile("fma.rn.f32x2 %0, %1, %2, %0;" : "+l"(A1) : "l"(W1), "l"(Z));
            }
        }
        asm volatile("st.shared.u64 [%0], %1;" :: "r"(gadr0), "l"(A0));
        asm volatile("st.shared.u64 [%0], %1;" :: "r"(gadr1), "l"(A1));
        __syncthreads();

        // ---- phase 2: activations + state update ----
        {
            float gi = gs[(0 * UPC + du2) * BPC + b2l];
            float gf = gs[(1 * UPC + du2) * BPC + b2l];
            float gg = gs[(2 * UPC + du2) * BPC + b2l];
            float go = gs[(3 * UPC + du2) * BPC + b2l];
            float iv = sigf(gi), fv = sigf(gf), gv = tanha(gg), ov = sigf(go);
            float cn = fmaf(fv, c_r, iv * gv);
            float hn = ov * tanha(cn);
            if (t < mylen) { c_r = cn; h_r = hn; }
            g_H[(t & 1) ^ 1][hidx] = h_r;
        }
        __syncthreads();   // all CTA h-writes issued

        if (t + 1 < maxlen) {
            // barrier ARRIVE (non-blocking part)
            if (tid == 0) {
                __threadfence();
                unsigned old = atomicAdd(&g_count, 1u);
                if (old == NCTA - 1) {
                    atomicExch(&g_count, 0u);
                    __threadfence();
                    g_release = (unsigned)(t + 1);
                }
            }
            // overlap with barrier: gather xe(t+1) ...
            if (tid < BPC) {
                int tok = x[(bb0 + tid) * NT + (t + 1)];
                const float4* e = (const float4*)(emb + (long)tok * EMBD);
                #pragma unroll
                for (int q = 0; q < EMBD / 4; q++) {
                    float4 v = e[q];
                    z[(q * 4 + 0) * BPC + tid] = v.x;
                    z[(q * 4 + 1) * BPC + tid] = v.y;
                    z[(q * 4 + 2) * BPC + tid] = v.z;
                    z[(q * 4 + 3) * BPC + tid] = v.w;
                }
            }
            __syncthreads();
            // ... and the input-projection GEMM for step t+1
            PACK2(A0, bias0);
            PACK2(A1, bias1);
            #pragma unroll 8
            for (int k = 0; k < EMBD; k++) {
                unsigned long long W0, W1, Z;
                asm volatile("ld.shared.v2.u64 {%0,%1}, [%2];"
                             : "=l"(W0), "=l"(W1) : "r"(wbase + (uint32_t)(k * 256)));
                asm volatile("ld.shared.u64 %0, [%1];"
                             : "=l"(Z) : "r"(zbase + (uint32_t)(k * 64)));
                asm volatile("fma.rn.f32x2 %0, %1, %2, %0;" : "+l"(A0) : "l"(W0), "l"(Z));
                asm volatile("fma.rn.f32x2 %0, %1, %2, %0;" : "+l"(A1) : "l"(W1), "l"(Z));
            }
            // barrier WAIT
            if (tid == 0) {
                while (g_release < (unsigned)(t + 1)) { }
                __threadfence();
            }
            __syncthreads();
        }
    }

    // final frozen h == reference out[:, -1, :]
    out[bg * HID + uu] = h_r;
}

extern "C" void kernel_launch(void* const* d_in, const int* in_sizes, int n_in,
                              void* d_out, int out_size) {
    const int*   x       = (const int*)d_in[0];
    const int*   lengths = (const int*)d_in[1];
    const float* emb     = (const float*)d_in[2];
    const float* W_ih    = (const float*)d_in[3];
    const float* W_hh    = (const float*)d_in[4];
    const float* b_ih    = (const float*)d_in[5];
    const float* b_hh    = (const float*)d_in[6];
    float* out = (float*)d_out;

    const int smem_bytes =
        (KTOT * NROWS * 2 + KTOT * BPC + NROWS * BPC + NROWS) * (int)sizeof(float)
        + (NB + 1) * (int)sizeof(int) + 32;

    cudaFuncSetAttribute(lstm_persist_kernel,
                         cudaFuncAttributeMaxDynamicSharedMemorySize, smem_bytes);

    lstm_init_kernel<<<1, 1>>>();
    lstm_persist_kernel<<<NCTA, NTHREADS, smem_bytes>>>(
        x, lengths, emb, W_ih, W_hh, b_ih, b_hh, out);
}